// round 1
// baseline (speedup 1.0000x reference)
#include <cuda_runtime.h>
#include <math.h>

#define Bq 8
#define Sq 12
#define Nq 4096
#define Fq 4
#define Hq 64
#define CHW 68                    // F + H
#define NCOL 544                  // Bq * CHW
#define NH  (Nq*Hq)               // 262144
#define N3H (Nq*3*Hq)             // 786432
#define ZOUT ((size_t)Bq*NH)      // offset of recon in output

// -------- persistent scratch (device globals; no allocation) --------
__device__ float g_h[Bq*NH];            // hidden state [b][n*H+hc]   (8 MB)
__device__ float g_cat[Nq*NCOL];        // GEMM rhs [k][b*68+f]       (8.7 MB)
__device__ float g_a[Nq*NCOL];          // GEMM out [m][b*68+f]       (8.7 MB)
__device__ float g_gate[Bq*N3H];        // sigmoid(gc1) torch-flat    (24 MB)
__device__ float g_tconv[Bq*NH];        // tanh(gc2)                  (8 MB)

__device__ __forceinline__ float sigf(float x){ return 1.f/(1.f+expf(-x)); }

// -------- h0 = broadcast struc_emb --------
__global__ void k_init_h(const float* __restrict__ se){
    int j = blockIdx.x*256 + threadIdx.x;
    if(j < NH){
        float v = se[j];
        #pragma unroll
        for(int b=0;b<Bq;b++) g_h[(size_t)b*NH + j] = v;
    }
}

// -------- build cat[k][b*68+f] = [x_t | h] --------
__global__ void k_cat(const float* __restrict__ X, int t){
    int idx = blockIdx.x*256 + threadIdx.x;      // Nq*NCOL elements exactly
    int n = idx / NCOL, c = idx - n*NCOL;
    int b = c / CHW,  f = c - b*CHW;
    float v;
    if(f < Fq) v = X[(size_t)((b*Sq + t)*Nq + n)*Fq + f];
    else       v = g_h[(size_t)b*NH + n*Hq + (f - Fq)];
    g_cat[idx] = v;
}

// -------- SGEMM: g_a[4096,544] = adj[4096,4096] @ g_cat[4096,544] --------
// BM=128, BN=64, BK=16, 256 threads, 8x4 per-thread tile, double buffered.
__global__ __launch_bounds__(256,2) void k_sgemm(const float* __restrict__ adj){
    __shared__ float Ash[2][16][132];   // [k][m], padded
    __shared__ float Bsh[2][16][64];    // [k][n]
    const int tid = threadIdx.x;
    const int m0 = blockIdx.x * 128;
    const int n0 = blockIdx.y * 64;
    const int ty = tid >> 4, tx = tid & 15;
    const int ar = tid >> 2, ac4 = tid & 3;
    const int br = tid >> 4, bc4 = tid & 15;
    const bool bval = (n0 + bc4*4) < NCOL;
    const float* aptr0 = adj + (size_t)(m0 + ar)*Nq + ac4*4;
    const float* aptr1 = aptr0 + (size_t)64*Nq;
    const float* bptr  = g_cat + (size_t)br*NCOL + n0 + bc4*4;

    float acc[8][4];
    #pragma unroll
    for(int i=0;i<8;i++)
        #pragma unroll
        for(int j=0;j<4;j++) acc[i][j] = 0.f;

    float4 rA0 = *(const float4*)aptr0;
    float4 rA1 = *(const float4*)aptr1;
    float4 rB  = bval ? *(const float4*)bptr : make_float4(0.f,0.f,0.f,0.f);

    Ash[0][ac4*4+0][ar] = rA0.x; Ash[0][ac4*4+1][ar] = rA0.y;
    Ash[0][ac4*4+2][ar] = rA0.z; Ash[0][ac4*4+3][ar] = rA0.w;
    Ash[0][ac4*4+0][ar+64] = rA1.x; Ash[0][ac4*4+1][ar+64] = rA1.y;
    Ash[0][ac4*4+2][ar+64] = rA1.z; Ash[0][ac4*4+3][ar+64] = rA1.w;
    *(float4*)&Bsh[0][br][bc4*4] = rB;
    __syncthreads();

    #pragma unroll 1
    for(int kt=0; kt<256; kt++){
        const int buf = kt & 1;
        if(kt < 255){
            const int ko = (kt+1)*16;
            rA0 = *(const float4*)(aptr0 + ko);
            rA1 = *(const float4*)(aptr1 + ko);
            rB  = bval ? *(const float4*)(bptr + (size_t)ko*NCOL)
                       : make_float4(0.f,0.f,0.f,0.f);
        }
        #pragma unroll
        for(int kk=0;kk<16;kk++){
            const float4 af0 = *(const float4*)&Ash[buf][kk][ty*8];
            const float4 af1 = *(const float4*)&Ash[buf][kk][ty*8+4];
            const float4 bf  = *(const float4*)&Bsh[buf][kk][tx*4];
            const float av[8] = {af0.x,af0.y,af0.z,af0.w,af1.x,af1.y,af1.z,af1.w};
            const float bv[4] = {bf.x,bf.y,bf.z,bf.w};
            #pragma unroll
            for(int i=0;i<8;i++)
                #pragma unroll
                for(int j=0;j<4;j++)
                    acc[i][j] += av[i]*bv[j];
        }
        __syncthreads();
        if(kt < 255){
            const int nb = buf^1;
            Ash[nb][ac4*4+0][ar] = rA0.x; Ash[nb][ac4*4+1][ar] = rA0.y;
            Ash[nb][ac4*4+2][ar] = rA0.z; Ash[nb][ac4*4+3][ar] = rA0.w;
            Ash[nb][ac4*4+0][ar+64] = rA1.x; Ash[nb][ac4*4+1][ar+64] = rA1.y;
            Ash[nb][ac4*4+2][ar+64] = rA1.z; Ash[nb][ac4*4+3][ar+64] = rA1.w;
            *(float4*)&Bsh[nb][br][bc4*4] = rB;
            __syncthreads();
        }
    }
    const int col = n0 + tx*4;
    if(col < NCOL){
        #pragma unroll
        for(int i=0;i<8;i++){
            float4 o; o.x=acc[i][0]; o.y=acc[i][1]; o.z=acc[i][2]; o.w=acc[i][3];
            *(float4*)&g_a[(size_t)(m0 + ty*8 + i)*NCOL + col] = o;
        }
    }
}

// -------- per-node weight GEMM + activations --------
// block: 32 nodes of one batch; smem: W combined [68][256], bias [256], a [68][36]
__global__ void k_gates(const float* __restrict__ W1, const float* __restrict__ b1,
                        const float* __restrict__ W2, const float* __restrict__ b2){
    extern __shared__ float sm[];
    float* Wc = sm;                 // 68*256
    float* bc = Wc + 68*256;        // 256
    float* at = bc + 256;           // 68*36 (padded, [f][i])
    const int tid = threadIdx.x;
    const int b  = blockIdx.y;
    const int m0 = blockIdx.x * 32;

    for(int idx=tid; idx<68*256; idx+=256){
        int f = idx >> 8, ch = idx & 255;
        Wc[idx] = (ch < 192) ? W1[f*192 + ch] : W2[f*64 + ch - 192];
    }
    bc[tid] = (tid < 192) ? b1[tid] : b2[tid - 192];
    for(int idx=tid; idx<32*68; idx+=256){
        int i = idx / 68, f = idx - i*68;
        at[f*36 + i] = g_a[(size_t)(m0+i)*NCOL + b*CHW + f];
    }
    __syncthreads();

    const int lane = tid & 31, wg = tid >> 5;   // wg: nodes wg*4..wg*4+3
    float acc[4][8];
    #pragma unroll
    for(int ii=0; ii<4; ii++)
        #pragma unroll
        for(int j=0; j<8; j++) acc[ii][j] = bc[lane + 32*j];

    #pragma unroll 4
    for(int f=0; f<68; f++){
        const float4 a4 = *(const float4*)&at[f*36 + wg*4];
        float w[8];
        #pragma unroll
        for(int j=0;j<8;j++) w[j] = Wc[f*256 + lane + 32*j];
        const float av[4] = {a4.x, a4.y, a4.z, a4.w};
        #pragma unroll
        for(int ii=0; ii<4; ii++)
            #pragma unroll
            for(int j=0; j<8; j++)
                acc[ii][j] += av[ii]*w[j];
    }
    #pragma unroll
    for(int ii=0; ii<4; ii++){
        const int node = m0 + wg*4 + ii;
        #pragma unroll
        for(int j=0; j<8; j++){
            const int ch = lane + 32*j;
            const float v = acc[ii][j];
            if(ch < 192) g_gate[(size_t)b*N3H + (size_t)node*192 + ch] = sigf(v);
            else         g_tconv[(size_t)b*NH + (size_t)node*64 + (ch-192)] = tanhf(v);
        }
    }
}

// -------- LSTM cell elementwise (torch-flat split f,i,o) --------
__global__ void k_cell(const float* __restrict__ se){
    int idx = blockIdx.x*256 + threadIdx.x;     // Bq*NH exactly
    int b = idx >> 18;                           // /NH (262144 = 2^18)
    int j = idx & (NH-1);
    const float* gg = g_gate + (size_t)b*N3H;
    float f = gg[j], i = gg[NH + j], o = gg[2*NH + j];
    float c = f*se[j] + i*g_tconv[idx];
    g_h[idx] = o * tanhf(c);
}

// -------- copy z to output --------
__global__ void k_copy_z(float* __restrict__ out){
    int idx = blockIdx.x*256 + threadIdx.x;     // Bq*NH exactly
    out[idx] = g_h[idx];
}

// -------- fused decoder: x_gates + 12-step LSTM + MLP head --------
// block = 256 threads = 8 warps, 2 rows per warp; W in smem [64][257] k-major.
#define WPAD 257
__global__ __launch_bounds__(256,2) void k_dec(
    const float* __restrict__ W_ih, const float* __restrict__ W_hh,
    const float* __restrict__ b_ih, const float* __restrict__ b_hh,
    const float* __restrict__ D1,   const float* __restrict__ bd1,
    const float* __restrict__ D2,   const float* __restrict__ bd2,
    float* __restrict__ out)
{
    extern __shared__ float sm[];
    float* Wsh = sm;                 // [64][257]
    float* hsh = Wsh + 64*WPAD;      // [16][64]
    float* D1s = hsh + 16*64;        // [64][32]
    const int tid = threadIdx.x, lane = tid & 31, w = tid >> 5;
    const int rA = blockIdx.x*16 + w*2;
    const int rB = rA + 1;

    for(int idx=tid; idx<256*64; idx+=256){
        int gc = idx >> 6, k = idx & 63;
        Wsh[k*WPAD + gc] = W_ih[idx];
    }
    for(int idx=tid; idx<64*32; idx+=256) D1s[idx] = D1[idx];

    float* hA = hsh + (w*2)*64;
    float* hB = hA + 64;
    hA[lane]    = g_h[(size_t)rA*64 + lane];
    hA[lane+32] = g_h[(size_t)rA*64 + lane + 32];
    hB[lane]    = g_h[(size_t)rB*64 + lane];
    hB[lane+32] = g_h[(size_t)rB*64 + lane + 32];
    __syncthreads();

    // x_gates (input contribution, constant across steps) -> registers
    float xgA[8], xgB[8];
    #pragma unroll
    for(int i=0;i<8;i++){
        int gc = lane + 32*i;
        float bb = b_ih[gc] + b_hh[gc];
        xgA[i] = bb; xgB[i] = bb;
    }
    for(int k=0;k<64;k++){
        float ha = hA[k], hb = hB[k];
        #pragma unroll
        for(int i=0;i<8;i++){
            float wv = Wsh[k*WPAD + lane + 32*i];
            xgA[i] += ha*wv; xgB[i] += hb*wv;
        }
    }
    __syncthreads();
    for(int idx=tid; idx<256*64; idx+=256){
        int gc = idx >> 6, k = idx & 63;
        Wsh[k*WPAD + gc] = W_hh[idx];
    }
    hA[lane]=0.f; hA[lane+32]=0.f; hB[lane]=0.f; hB[lane+32]=0.f;
    float cA0=0.f, cA1=0.f, cB0=0.f, cB1=0.f;
    const float bd1r = bd1[lane];
    const float d2r  = D2[lane];
    const float bd2r = bd2[0];
    __syncthreads();

    for(int s=0; s<Sq; s++){
        float aA[8], aB[8];
        #pragma unroll
        for(int i=0;i<8;i++){ aA[i]=xgA[i]; aB[i]=xgB[i]; }
        for(int k=0;k<64;k++){
            float ha = hA[k], hb = hB[k];
            #pragma unroll
            for(int i=0;i<8;i++){
                float wv = Wsh[k*WPAD + lane + 32*i];
                aA[i] += ha*wv; aB[i] += hb*wv;
            }
        }
        // torch gate order i,f,g,o; lane covers hc=lane (even regs) & hc=lane+32 (odd regs)
        float hA0,hA1,hB0,hB1;
        {
            float ig=sigf(aA[0]), fg=sigf(aA[2]), gg=tanhf(aA[4]), og=sigf(aA[6]);
            cA0 = fg*cA0 + ig*gg; hA0 = og*tanhf(cA0);
            ig=sigf(aA[1]); fg=sigf(aA[3]); gg=tanhf(aA[5]); og=sigf(aA[7]);
            cA1 = fg*cA1 + ig*gg; hA1 = og*tanhf(cA1);
            ig=sigf(aB[0]); fg=sigf(aB[2]); gg=tanhf(aB[4]); og=sigf(aB[6]);
            cB0 = fg*cB0 + ig*gg; hB0 = og*tanhf(cB0);
            ig=sigf(aB[1]); fg=sigf(aB[3]); gg=tanhf(aB[5]); og=sigf(aB[7]);
            cB1 = fg*cB1 + ig*gg; hB1 = og*tanhf(cB1);
        }
        __syncwarp();
        hA[lane]=hA0; hA[lane+32]=hA1; hB[lane]=hB0; hB[lane+32]=hB1;
        __syncwarp();

        // d = relu(h@D1+bd1)@D2 + bd2 ; lane = hidden index p (H/2 = 32)
        float uA = bd1r, uB = bd1r;
        for(int k=0;k<64;k++){
            float dv = D1s[k*32 + lane];
            uA += hA[k]*dv; uB += hB[k]*dv;
        }
        uA = fmaxf(uA, 0.f)*d2r;
        uB = fmaxf(uB, 0.f)*d2r;
        #pragma unroll
        for(int off=16; off; off>>=1){
            uA += __shfl_xor_sync(0xffffffffu, uA, off);
            uB += __shfl_xor_sync(0xffffffffu, uB, off);
        }
        if(lane == 0){
            out[ZOUT + (size_t)rA*Sq + s] = uA + bd2r;
            out[ZOUT + (size_t)rB*Sq + s] = uB + bd2r;
        }
    }
}

// ------------------------------------------------------------------
extern "C" void kernel_launch(void* const* d_in, const int* in_sizes, int n_in,
                              void* d_out, int out_size)
{
    const float* X    = (const float*)d_in[0];
    const float* adj  = (const float*)d_in[1];
    const float* se   = (const float*)d_in[2];
    const float* W1   = (const float*)d_in[3];
    const float* b1   = (const float*)d_in[4];
    const float* W2   = (const float*)d_in[5];
    const float* b2   = (const float*)d_in[6];
    const float* W_ih = (const float*)d_in[7];
    const float* W_hh = (const float*)d_in[8];
    const float* b_ih = (const float*)d_in[9];
    const float* b_hh = (const float*)d_in[10];
    const float* D1   = (const float*)d_in[11];
    const float* bd1  = (const float*)d_in[12];
    const float* D2   = (const float*)d_in[13];
    const float* bd2  = (const float*)d_in[14];
    float* out = (float*)d_out;

    const int smem_gates = (68*256 + 256 + 68*36) * 4;                 // 80448
    const int smem_dec   = (64*WPAD + 16*64 + 64*32) * 4;              // 78080
    cudaFuncSetAttribute(k_gates, cudaFuncAttributeMaxDynamicSharedMemorySize, smem_gates);
    cudaFuncSetAttribute(k_dec,   cudaFuncAttributeMaxDynamicSharedMemorySize, smem_dec);

    k_init_h<<<NH/256, 256>>>(se);
    for(int t=0; t<Sq; t++){
        k_cat  <<<(Nq*NCOL)/256, 256>>>(X, t);
        k_sgemm<<<dim3(Nq/128, (NCOL+63)/64), 256>>>(adj);
        k_gates<<<dim3(Nq/32, Bq), 256, smem_gates>>>(W1, b1, W2, b2);
        k_cell <<<(Bq*NH)/256, 256>>>(se);
    }
    k_copy_z<<<(Bq*NH)/256, 256>>>(out);
    k_dec<<<(Bq*Nq)/16, 256, smem_dec>>>(W_ih, W_hh, b_ih, b_hh, D1, bd1, D2, bd2, out);
}